// round 8
// baseline (speedup 1.0000x reference)
#include <cuda_runtime.h>
#include <math.h>

#define TT   200
#define BB   1024
#define DD   128
#define TOBS 140
#define LL   20
#define LATD 32
#define GU   200
#define UNI  100
#define GIN  168      /* effective K: y(40)+x(128); ones-row folded into colsum */
#define ROWS 4
#define NTHR 512
#define NBLK (BB / ROWS)   /* 256 */

#define KH   84       /* K per half for GRU l1 split-2 */

#define SM_FLOATS 26560

__device__ float g_colsum[3 * GU];

__device__ __forceinline__ float fast_tanh(float x) {
    float xc = fminf(fmaxf(x, -9.f), 9.f);
    float e = __expf(2.f * xc);
    return __fdividef(e - 1.f, e + 1.f);
}
__device__ __forceinline__ float fast_sigmoid(float x) {
    return __fdividef(1.f, 1.f + __expf(-x));
}

__global__ void colsum_kernel(const float* __restrict__ uw1,
                              const float* __restrict__ rw1,
                              const float* __restrict__ nw1) {
    int j = threadIdx.x;
    const float* w = (blockIdx.x == 0) ? uw1 : (blockIdx.x == 1 ? rw1 : nw1);
    float sacc = 0.f;
    for (int k = GIN; k < 2 * LL + 2 * DD; ++k) sacc += w[k * GU + j];
    g_colsum[blockIdx.x * GU + j] = sacc;
}

// ---- GRU layer1 dual (u,r): K-split 2, 4-row acc, prefetch tiles of 6 ----
__device__ __forceinline__ void gru_l1_dual_ks(const float* __restrict__ wA,
                                               const float* __restrict__ wB,
                                               const float* __restrict__ ycT,
                                               float* __restrict__ pL1,
                                               int j, int ks) {
    float aA[4], aB[4];
#pragma unroll
    for (int r = 0; r < 4; ++r) { aA[r] = 0.f; aB[r] = 0.f; }
    const float* pA = wA + (size_t)ks * KH * GU + j;
    const float* pB = wB + (size_t)ks * KH * GU + j;
    const float* yc = ycT + ks * KH * 4;
    float wa[6], wb[6];
#pragma unroll
    for (int kk = 0; kk < 6; ++kk) { wa[kk] = pA[kk * GU]; wb[kk] = pB[kk * GU]; }
#pragma unroll 1
    for (int t = 0; t < 14; ++t) {
        float na[6], nb[6];
        if (t + 1 < 14) {
#pragma unroll
            for (int kk = 0; kk < 6; ++kk) {
                na[kk] = pA[((t + 1) * 6 + kk) * GU];
                nb[kk] = pB[((t + 1) * 6 + kk) * GU];
            }
        }
#pragma unroll
        for (int kk = 0; kk < 6; ++kk) {
            int k = t * 6 + kk;
            float4 y0 = *(const float4*)(yc + k * 4);
            float w0 = wa[kk], w1 = wb[kk];
            aA[0] += y0.x * w0; aA[1] += y0.y * w0; aA[2] += y0.z * w0; aA[3] += y0.w * w0;
            aB[0] += y0.x * w1; aB[1] += y0.y * w1; aB[2] += y0.z * w1; aB[3] += y0.w * w1;
        }
        if (t + 1 < 14) {
#pragma unroll
            for (int kk = 0; kk < 6; ++kk) { wa[kk] = na[kk]; wb[kk] = nb[kk]; }
        }
    }
    *(float4*)(pL1 + ks * 800 + j * 4)        = make_float4(aA[0], aA[1], aA[2], aA[3]);
    *(float4*)(pL1 + 1600 + ks * 800 + j * 4) = make_float4(aB[0], aB[1], aB[2], aB[3]);
}

// ---- GRU n layer1: K-split 2, 4-row acc, prefetch tiles of 12 ----
__device__ __forceinline__ void gru_l1_single_ks(const float* __restrict__ wA,
                                                 const float* __restrict__ ycT,
                                                 float* __restrict__ pN,
                                                 int j, int ks) {
    float aA[4];
#pragma unroll
    for (int r = 0; r < 4; ++r) aA[r] = 0.f;
    const float* pA = wA + (size_t)ks * KH * GU + j;
    const float* yc = ycT + ks * KH * 4;
    float wa[12];
#pragma unroll
    for (int kk = 0; kk < 12; ++kk) wa[kk] = pA[kk * GU];
#pragma unroll 1
    for (int t = 0; t < 7; ++t) {
        float na[12];
        if (t + 1 < 7) {
#pragma unroll
            for (int kk = 0; kk < 12; ++kk) na[kk] = pA[((t + 1) * 12 + kk) * GU];
        }
#pragma unroll
        for (int kk = 0; kk < 12; ++kk) {
            int k = t * 12 + kk;
            float4 y0 = *(const float4*)(yc + k * 4);
            float w0 = wa[kk];
            aA[0] += y0.x * w0; aA[1] += y0.y * w0; aA[2] += y0.z * w0; aA[3] += y0.w * w0;
        }
        if (t + 1 < 7) {
#pragma unroll
            for (int kk = 0; kk < 12; ++kk) wa[kk] = na[kk];
        }
    }
    *(float4*)(pN + ks * 800 + j * 4) = make_float4(aA[0], aA[1], aA[2], aA[3]);
}

// encoder MLP: l1 direct (200 thr, 2 rows each), l2 partials (200 thr, 4-row)
__device__ __forceinline__ void enc_eval(const float* __restrict__ ew1,
                                         const float* __restrict__ eb1,
                                         const float* __restrict__ ew2,
                                         const float* __restrict__ ytmpT,
                                         float* __restrict__ hencT,
                                         float* __restrict__ pe, int tid) {
    if (tid < 200) {
        int j = tid % UNI, rq = tid / UNI;   // rows 2rq, 2rq+1
        float a0 = eb1[j], a1 = a0;
#pragma unroll
        for (int k = 0; k < LL; ++k) {
            float w = ew1[k * UNI + j];
            float2 yv = *(const float2*)(ytmpT + k * 4 + 2 * rq);
            a0 += yv.x * w; a1 += yv.y * w;
        }
        *(float2*)(hencT + j * 4 + 2 * rq) = make_float2(fast_tanh(a0), fast_tanh(a1));
    }
    __syncthreads();
    if (tid < 200) {
        int jj = tid % LL, ks = tid / LL;   // ks 0..9, K=10
        float a[4];
#pragma unroll
        for (int r = 0; r < 4; ++r) a[r] = 0.f;
#pragma unroll
        for (int k = ks * 10; k < ks * 10 + 10; ++k) {
            float w = ew2[k * LL + jj];
            float4 y0 = *(const float4*)(hencT + k * 4);
            a[0] += y0.x * w; a[1] += y0.y * w; a[2] += y0.z * w; a[3] += y0.w * w;
        }
        *(float4*)(pe + ks * 80 + jj * 4) = make_float4(a[0], a[1], a[2], a[3]);
    }
    __syncthreads();
}

#define ENC_K(tidv) (pe[(tidv)] + pe[80 + (tidv)] + pe[160 + (tidv)] + pe[240 + (tidv)] + \
                     pe[320 + (tidv)] + pe[400 + (tidv)] + pe[480 + (tidv)] + pe[560 + (tidv)] + \
                     pe[640 + (tidv)] + pe[720 + (tidv)] + eb2[(tidv) >> 2])

// decoder MLP (4-row): l1 direct 200 thr; l2 400 thr K-split 4; l3 320 thr K-split 10
__device__ __forceinline__ void dec_eval(const float* __restrict__ dw1,
                                         const float* __restrict__ db1,
                                         const float* __restrict__ dw2,
                                         const float* __restrict__ db2,
                                         const float* __restrict__ dw3,
                                         const float* __restrict__ zin,
                                         float* __restrict__ h1T,
                                         float* __restrict__ h2T,
                                         float* __restrict__ pd2,
                                         float* __restrict__ pd3, int tid) {
    if (tid < 200) {
        int j = tid % UNI, rq = tid / UNI;
        float a0 = db1[j], a1 = a0;
#pragma unroll 8
        for (int k = 0; k < LATD; ++k) {
            float w = dw1[k * UNI + j];
            float2 zv = *(const float2*)(zin + k * 4 + 2 * rq);
            a0 += zv.x * w; a1 += zv.y * w;
        }
        *(float2*)(h1T + j * 4 + 2 * rq) = make_float2(fast_tanh(a0), fast_tanh(a1));
    }
    __syncthreads();
    if (tid < 400) {
        int j = tid % UNI, ks = tid / UNI;   // ks 0..3, K=25
        float a[4];
#pragma unroll
        for (int r = 0; r < 4; ++r) a[r] = 0.f;
#pragma unroll 5
        for (int k = ks * 25; k < ks * 25 + 25; ++k) {
            float w = dw2[k * UNI + j];
            float4 z0 = *(const float4*)(h1T + k * 4);
            a[0] += z0.x * w; a[1] += z0.y * w; a[2] += z0.z * w; a[3] += z0.w * w;
        }
        *(float4*)(pd2 + ks * 400 + j * 4) = make_float4(a[0], a[1], a[2], a[3]);
    }
    __syncthreads();
    for (int i = tid; i < 400; i += NTHR)
        h2T[i] = fast_tanh(pd2[i] + pd2[400 + i] + pd2[800 + i] + pd2[1200 + i] + db2[i >> 2]);
    __syncthreads();
    if (tid < 320) {
        int jj = tid % LATD, ks = tid / LATD;  // ks 0..9, K=10
        float a[4];
#pragma unroll
        for (int r = 0; r < 4; ++r) a[r] = 0.f;
#pragma unroll
        for (int k = ks * 10; k < ks * 10 + 10; ++k) {
            float w = dw3[k * LATD + jj];
            float4 z0 = *(const float4*)(h2T + k * 4);
            a[0] += z0.x * w; a[1] += z0.y * w; a[2] += z0.z * w; a[3] += z0.w * w;
        }
        *(float4*)(pd3 + ks * 128 + jj * 4) = make_float4(a[0], a[1], a[2], a[3]);
    }
    __syncthreads();
}

#define DEC_K(tidv) (pd3[(tidv)] + pd3[128 + (tidv)] + pd3[256 + (tidv)] + pd3[384 + (tidv)] + \
                     pd3[512 + (tidv)] + pd3[640 + (tidv)] + pd3[768 + (tidv)] + pd3[896 + (tidv)] + \
                     pd3[1024 + (tidv)] + pd3[1152 + (tidv)] + db3[(tidv) >> 2])

extern "C" __global__ void __launch_bounds__(NTHR, 2)
latent_ode_main(const float* __restrict__ truth, const float* __restrict__ tarr,
                const int* __restrict__ obs_idx, const float* __restrict__ eps,
                const float* __restrict__ ew1g, const float* __restrict__ eb1g,
                const float* __restrict__ ew2g, const float* __restrict__ eb2g,
                const float* __restrict__ uw1, const float* __restrict__ ub1g,
                const float* __restrict__ uw2g, const float* __restrict__ ub2g,
                const float* __restrict__ rw1, const float* __restrict__ rb1g,
                const float* __restrict__ rw2g, const float* __restrict__ rb2g,
                const float* __restrict__ nw1, const float* __restrict__ nb1g,
                const float* __restrict__ nw2g, const float* __restrict__ nb2g,
                const float* __restrict__ z0w1, const float* __restrict__ z0b1,
                const float* __restrict__ z0w2, const float* __restrict__ z0b2,
                const float* __restrict__ dw1g, const float* __restrict__ db1g,
                const float* __restrict__ dw2g, const float* __restrict__ db2g,
                const float* __restrict__ dw3g, const float* __restrict__ db3g,
                const float* __restrict__ owg, const float* __restrict__ obg,
                float* __restrict__ out) {
    extern __shared__ float s[];
    const int tid = threadIdx.x;
    const int b0 = blockIdx.x * ROWS;

    float* zT = s;           // [32][4] k-major, persistent
    float* P  = s + 256;

    // ---------------- encoder smem layout (uw2/rw2 streamed from gmem) ----------------
    float* ew1   = P;            // 2000
    float* ew2   = P + 2000;     // 2000
    float* eb1   = P + 4000;     // 100
    float* eb2   = P + 4100;     // 20 (pad to 4128)
    float* nw2   = P + 4128;     // 8000
    float* ub1   = P + 12128;    // 200
    float* rb1   = P + 12328;    // 200
    float* nb1   = P + 12528;    // 200
    float* ub2   = P + 12728;    // 40
    float* rb2   = P + 12768;    // 40
    float* nb2   = P + 12808;    // 40
    float* csu   = P + 12848;    // 200
    float* csr   = P + 13048;    // 200
    float* csn   = P + 13248;    // 200
    float* y     = P + 13448;    // 160  [4][40]
    float* ycT   = P + 13608;    // 672  [168][4]
    float* ytmpT = P + 14280;    // 80
    float* accT  = P + 14360;    // 80
    float* hencT = P + 14440;    // 400
    float* pe    = P + 14840;    // 800  [10][20][4]
    float* hTa   = P + 15640;    // 800  [200][4]
    float* hTb   = P + 16440;    // 800
    float* pL1   = P + 17240;    // 3200 [2 gates][2 ks][200][4]
    float* p2    = P + 20440;    // 1280 [2][4][40][4]
    float* pn    = P + 21720;    // 1280 [8][40][4]
    float* u_    = P + 23000;    // 160  [4][40]
    // shared tail beyond both alias regions:
    float* dts   = P + 25824;    // 140
    float* iob   = P + 25964;    // 140
    float* ddt   = P + 26104;    // 200 (end 26304)

    for (int i = tid; i < 2000; i += NTHR) { ew1[i] = ew1g[i]; ew2[i] = ew2g[i]; }
    for (int i = tid; i < 100;  i += NTHR) eb1[i] = eb1g[i];
    for (int i = tid; i < 20;   i += NTHR) eb2[i] = eb2g[i];
    for (int i = tid; i < 8000; i += NTHR) nw2[i] = nw2g[i];
    for (int i = tid; i < 200;  i += NTHR) {
        ub1[i] = ub1g[i]; rb1[i] = rb1g[i]; nb1[i] = nb1g[i];
        csu[i] = g_colsum[i]; csr[i] = g_colsum[200 + i]; csn[i] = g_colsum[400 + i];
    }
    for (int i = tid; i < 40; i += NTHR) { ub2[i] = ub2g[i]; rb2[i] = rb2g[i]; nb2[i] = nb2g[i]; }
    for (int i = tid; i < ROWS * 40; i += NTHR) y[i] = 0.f;
    for (int i = tid; i < TOBS; i += NTHR) {
        int io = obs_idx[TOBS - 1 - i];
        iob[i] = __int_as_float(io);
        dts[i] = (i > 0) ? (tarr[io] - tarr[obs_idx[TOBS - i]]) : 0.f;
    }
    for (int i = tid; i < TT - 1; i += NTHR) ddt[i] = tarr[i + 1] - tarr[i];
    __syncthreads();

    // ================= encoder scan =================
    for (int st = 0; st < TOBS; ++st) {
        int io = __float_as_int(iob[st]);
        float dt = dts[st];

        // ---- RK4 on ym ----
        if (tid < 80) { int j = tid >> 2, r = tid & 3; ytmpT[tid] = y[r * 40 + j]; }
        __syncthreads();
        enc_eval(ew1, eb1, ew2, ytmpT, hencT, pe, tid);
        if (tid < 80) {
            int j = tid >> 2, r = tid & 3;
            float kv = ENC_K(tid);
            accT[tid] = kv;
            ytmpT[tid] = y[r * 40 + j] + 0.5f * dt * kv;
        }
        __syncthreads();
        enc_eval(ew1, eb1, ew2, ytmpT, hencT, pe, tid);
        if (tid < 80) {
            int j = tid >> 2, r = tid & 3;
            float kv = ENC_K(tid);
            accT[tid] += 2.f * kv;
            ytmpT[tid] = y[r * 40 + j] + 0.5f * dt * kv;
        }
        __syncthreads();
        enc_eval(ew1, eb1, ew2, ytmpT, hencT, pe, tid);
        if (tid < 80) {
            int j = tid >> 2, r = tid & 3;
            float kv = ENC_K(tid);
            accT[tid] += 2.f * kv;
            ytmpT[tid] = y[r * 40 + j] + dt * kv;
        }
        __syncthreads();
        enc_eval(ew1, eb1, ew2, ytmpT, hencT, pe, tid);
        if (tid < 80) {
            int j = tid >> 2, r = tid & 3;
            float kv = ENC_K(tid);
            y[r * 40 + j] += dt * (1.f / 6.f) * (accT[tid] + kv);
        }
        __syncthreads();

        // ---- build ycT ----
        for (int i = tid; i < GIN * ROWS; i += NTHR) {
            int k = i >> 2, r = i & 3;
            ycT[i] = (k < 40) ? y[r * 40 + k]
                              : truth[(size_t)io * (BB * DD) + (size_t)(b0 + r) * DD + (k - 40)];
        }
        __syncthreads();

        // ---- u,r layer1 (K-split 2, 400 thr) ----
        if (tid < 400)
            gru_l1_dual_ks(uw1, rw1, ycT, pL1, tid % GU, tid / GU);
        __syncthreads();
        // reduce + bias + tanh (1600 elems)
        for (int i = tid; i < 1600; i += NTHR) {
            int g = i / 800, rem = i % 800, j = rem >> 2;
            float base = g ? (csr[j] + rb1[j]) : (csu[j] + ub1[j]);
            float v = pL1[g * 1600 + rem] + pL1[g * 1600 + 800 + rem] + base;
            (g ? hTb : hTa)[rem] = fast_tanh(v);
        }
        __syncthreads();

        // ---- u,r layer2 (K-split 4, 320 thr; weights streamed from gmem) ----
        if (tid < 320) {
            int g = tid / 160, rem = tid % 160, jj = rem % 40, ks = rem / 40;  // K=50
            const float* hT = g ? hTb : hTa;
            const float* w2 = g ? rw2g : uw2g;
            int kbase = ks * 50;
            float a[4];
#pragma unroll
            for (int r = 0; r < 4; ++r) a[r] = 0.f;
            float wbuf[5];
#pragma unroll
            for (int kk = 0; kk < 5; ++kk) wbuf[kk] = w2[(kbase + kk) * 40 + jj];
#pragma unroll 1
            for (int t = 0; t < 10; ++t) {
                float nb[5];
                if (t + 1 < 10) {
#pragma unroll
                    for (int kk = 0; kk < 5; ++kk)
                        nb[kk] = w2[(kbase + (t + 1) * 5 + kk) * 40 + jj];
                }
#pragma unroll
                for (int kk = 0; kk < 5; ++kk) {
                    int k = kbase + t * 5 + kk;
                    float4 h0 = *(const float4*)(hT + k * 4);
                    float w = wbuf[kk];
                    a[0] += h0.x * w; a[1] += h0.y * w; a[2] += h0.z * w; a[3] += h0.w * w;
                }
                if (t + 1 < 10) {
#pragma unroll
                    for (int kk = 0; kk < 5; ++kk) wbuf[kk] = nb[kk];
                }
            }
            *(float4*)(p2 + g * 640 + ks * 160 + jj * 4) = make_float4(a[0], a[1], a[2], a[3]);
        }
        __syncthreads();
        // reduce + sigmoid; g==1 (r gate) scales ycT in place, g==0 stores u_
        if (tid < 320) {
            int g = tid / 160, rem = tid % 160, jj = rem >> 2, r = rem & 3;
            const float* p = p2 + g * 640;
            float a = p[rem] + p[160 + rem] + p[320 + rem] + p[480 + rem] + (g ? rb2 : ub2)[jj];
            float sg = fast_sigmoid(a);
            if (g) ycT[rem] *= sg;   // rem == jj*4+r, jj<40: y-part of ycT
            else   u_[r * 40 + jj] = sg;
        }
        __syncthreads();

        // ---- n layer1 (K-split 2, 400 thr; ycT already r-scaled) ----
        if (tid < 400)
            gru_l1_single_ks(nw1, ycT, pL1, tid % GU, tid / GU);
        __syncthreads();
        for (int i = tid; i < 800; i += NTHR) {
            int j = i >> 2;
            hTa[i] = fast_tanh(pL1[i] + pL1[800 + i] + csn[j] + nb1[j]);
        }
        __syncthreads();

        // ---- n layer2 (K-split 8, 320 thr; nw2 in smem) ----
        if (tid < 320) {
            int jj = tid % 40, ks = tid / 40;   // K=25
            float a[4];
#pragma unroll
            for (int r = 0; r < 4; ++r) a[r] = 0.f;
#pragma unroll 5
            for (int k = ks * 25; k < ks * 25 + 25; ++k) {
                float w = nw2[k * 40 + jj];
                float4 h0 = *(const float4*)(hTa + k * 4);
                a[0] += h0.x * w; a[1] += h0.y * w; a[2] += h0.z * w; a[3] += h0.w * w;
            }
            *(float4*)(pn + ks * 160 + jj * 4) = make_float4(a[0], a[1], a[2], a[3]);
        }
        __syncthreads();
        // reduce + state update
        if (tid < 160) {
            int jj = tid >> 2, r = tid & 3;
            float a = pn[tid] + pn[160 + tid] + pn[320 + tid] + pn[480 + tid]
                    + pn[640 + tid] + pn[800 + tid] + pn[960 + tid] + pn[1120 + tid] + nb2[jj];
            float val = (jj < LL) ? a : fabsf(a);
            float uu = u_[r * 40 + jj];
            y[r * 40 + jj] = (1.f - uu) * val + uu * y[r * 40 + jj];
        }
        __syncthreads();
    }

    // ================= z0 head (once) =================
    if (tid < 400) {
        int r = tid / UNI, j = tid % UNI;
        float a = z0b1[j];
#pragma unroll 4
        for (int k = 0; k < 40; ++k) a += y[r * 40 + k] * z0w1[k * UNI + j];
        hencT[r * UNI + j] = fast_tanh(a);
    }
    __syncthreads();
    if (tid < 256) {
        int r = tid / 64, j = tid % 64;
        float a = z0b2[j];
#pragma unroll 4
        for (int k = 0; k < UNI; ++k) a += hencT[r * UNI + k] * z0w2[k * 64 + j];
        hTa[r * 64 + j] = a;
    }
    __syncthreads();
    if (tid < 128) {
        int r = tid >> 5, j = tid & 31;
        float m = hTa[r * 64 + j];
        float sd = fabsf(hTa[r * 64 + 32 + j]);
        zT[j * 4 + r] = m + eps[(size_t)(b0 + r) * LATD + j] * sd;
    }
    __syncthreads();

    // ---------------- decoder smem layout (aliases P; dts/iob/ddt beyond) ----------------
    float* dw1   = P;             // 3200
    float* dw2   = P + 3200;      // 10000
    float* dw3   = P + 13200;     // 3200
    float* db1   = P + 16400;     // 100
    float* db2   = P + 16500;     // 100
    float* db3   = P + 16600;     // 32
    float* ow    = P + 16632;     // 4096
    float* ob    = P + 20728;     // 128
    float* h1T   = P + 20856;     // 400
    float* h2T   = P + 21256;     // 400
    float* ztmpT = P + 21656;     // 128
    float* zacc  = P + 21784;     // 128
    float* pd2   = P + 21912;     // 1600 [4][100][4]
    float* pd3   = P + 23512;     // 1280 [10][32][4]
    float* pp    = P + 24792;     // 1024 [2][128][4]  (end 25816)

    for (int i = tid; i < 3200;  i += NTHR) { dw1[i] = dw1g[i]; dw3[i] = dw3g[i]; }
    for (int i = tid; i < 10000; i += NTHR) dw2[i] = dw2g[i];
    for (int i = tid; i < 100;   i += NTHR) { db1[i] = db1g[i]; db2[i] = db2g[i]; }
    for (int i = tid; i < 32;    i += NTHR) db3[i] = db3g[i];
    for (int i = tid; i < 4096;  i += NTHR) ow[i] = owg[i];
    for (int i = tid; i < 128;   i += NTHR) ob[i] = obg[i];
    __syncthreads();

    // ================= decoder scan + projection =================
    for (int ti = 0; ti < TT; ++ti) {
        if (ti > 0) {
            float dt = ddt[ti - 1];
            if (tid < 128) ztmpT[tid] = zT[tid];
            __syncthreads();
            dec_eval(dw1, db1, dw2, db2, dw3, ztmpT, h1T, h2T, pd2, pd3, tid);
            if (tid < 128) {
                float kv = DEC_K(tid);
                zacc[tid] = kv;
                ztmpT[tid] = zT[tid] + 0.5f * dt * kv;
            }
            __syncthreads();
            dec_eval(dw1, db1, dw2, db2, dw3, ztmpT, h1T, h2T, pd2, pd3, tid);
            if (tid < 128) {
                float kv = DEC_K(tid);
                zacc[tid] += 2.f * kv;
                ztmpT[tid] = zT[tid] + 0.5f * dt * kv;
            }
            __syncthreads();
            dec_eval(dw1, db1, dw2, db2, dw3, ztmpT, h1T, h2T, pd2, pd3, tid);
            if (tid < 128) {
                float kv = DEC_K(tid);
                zacc[tid] += 2.f * kv;
                ztmpT[tid] = zT[tid] + dt * kv;
            }
            __syncthreads();
            dec_eval(dw1, db1, dw2, db2, dw3, ztmpT, h1T, h2T, pd2, pd3, tid);
            if (tid < 128) {
                float kv = DEC_K(tid);
                zT[tid] += dt * (1.f / 6.f) * (zacc[tid] + kv);
            }
            __syncthreads();
        }

        // output projection (K-split 2, 256 thr, 4-row)
        if (tid < 256) {
            int d = tid % DD, h = tid / DD;   // K=16 per half
            float a[4];
#pragma unroll
            for (int r = 0; r < 4; ++r) a[r] = 0.f;
#pragma unroll
            for (int k = h * 16; k < h * 16 + 16; ++k) {
                float w = ow[k * DD + d];
                float4 z0 = *(const float4*)(zT + k * 4);
                a[0] += z0.x * w; a[1] += z0.y * w; a[2] += z0.z * w; a[3] += z0.w * w;
            }
            *(float4*)(pp + h * 512 + d * 4) = make_float4(a[0], a[1], a[2], a[3]);
        }
        __syncthreads();
        if (tid < DD) {
            int d = tid;
#pragma unroll
            for (int r = 0; r < 4; ++r)
                out[(size_t)(b0 + r) * (TT * DD) + (size_t)ti * DD + d] =
                    pp[d * 4 + r] + pp[512 + d * 4 + r] + ob[d];
        }
        __syncthreads();
    }
}

extern "C" void kernel_launch(void* const* d_in, const int* in_sizes, int n_in,
                              void* d_out, int out_size) {
    (void)in_sizes; (void)n_in; (void)out_size;
    size_t smem = (size_t)SM_FLOATS * sizeof(float);
    cudaFuncSetAttribute(latent_ode_main, cudaFuncAttributeMaxDynamicSharedMemorySize, (int)smem);

    colsum_kernel<<<3, GU>>>((const float*)d_in[8], (const float*)d_in[12], (const float*)d_in[16]);

    latent_ode_main<<<NBLK, NTHR, smem>>>(
        (const float*)d_in[0], (const float*)d_in[1], (const int*)d_in[2], (const float*)d_in[3],
        (const float*)d_in[4],  (const float*)d_in[5],  (const float*)d_in[6],  (const float*)d_in[7],
        (const float*)d_in[8],  (const float*)d_in[9],  (const float*)d_in[10], (const float*)d_in[11],
        (const float*)d_in[12], (const float*)d_in[13], (const float*)d_in[14], (const float*)d_in[15],
        (const float*)d_in[16], (const float*)d_in[17], (const float*)d_in[18], (const float*)d_in[19],
        (const float*)d_in[20], (const float*)d_in[21], (const float*)d_in[22], (const float*)d_in[23],
        (const float*)d_in[24], (const float*)d_in[25], (const float*)d_in[26], (const float*)d_in[27],
        (const float*)d_in[28], (const float*)d_in[29], (const float*)d_in[30], (const float*)d_in[31],
        (float*)d_out);
}

// round 9
// speedup vs baseline: 1.0362x; 1.0362x over previous
#include <cuda_runtime.h>
#include <math.h>

#define TT   200
#define BB   1024
#define DD   128
#define TOBS 140
#define LL   20
#define LATD 32
#define GU   200
#define UNI  100
#define GIN  168      /* effective K: y(40)+x(128); ones-row folded into colsum */
#define ROWS 4
#define NTHR 384
#define NBLK (BB / ROWS)   /* 256 */

#define KH   84       /* K per half for GRU l1 split-2 */

#define SM_FLOATS 26560

__device__ float g_colsum[3 * GU];
__device__ float g_w1t[3][GIN * GU];   // pair-interleaved: [k][2p+h] = w1[k][p+100h]
__device__ float g_w2t[2][GU * 40];    // pair-interleaved: [k][2jj+h] = w2[k][jj+20h]

__device__ __forceinline__ float fast_tanh(float x) {
    float xc = fminf(fmaxf(x, -9.f), 9.f);
    float e = __expf(2.f * xc);
    return __fdividef(e - 1.f, e + 1.f);
}
__device__ __forceinline__ float fast_sigmoid(float x) {
    return __fdividef(1.f, 1.f + __expf(-x));
}

// prep: colsum + weight transposes (blockIdx.x = gate g)
__global__ void prep_kernel(const float* __restrict__ uw1,
                            const float* __restrict__ rw1,
                            const float* __restrict__ nw1,
                            const float* __restrict__ uw2,
                            const float* __restrict__ rw2) {
    int g = blockIdx.x;
    const float* w1 = (g == 0) ? uw1 : (g == 1 ? rw1 : nw1);
    int tid = threadIdx.x;
    if (tid < GU) {
        float sacc = 0.f;
        for (int k = GIN; k < 2 * LL + 2 * DD; ++k) sacc += w1[k * GU + tid];
        g_colsum[g * GU + tid] = sacc;
    }
    for (int i = tid; i < GIN * GU; i += blockDim.x) {
        int k = i / GU, j = i % GU;
        g_w1t[g][k * GU + 2 * (j % 100) + (j / 100)] = w1[i];
    }
    if (g < 2) {
        const float* w2 = (g == 0) ? uw2 : rw2;
        for (int i = tid; i < GU * 40; i += blockDim.x) {
            int k = i / 40, j = i % 40;
            g_w2t[g][k * 40 + 2 * (j % 20) + (j / 20)] = w2[i];
        }
    }
}

// ---- GRU l1 dual (u,r): j-paired, K-split 2, ping-pong prefetch (tiles of 6) ----
__device__ __forceinline__ void gru_l1_dual_ks(const float* __restrict__ ycT,
                                               float* __restrict__ pL1,
                                               int p, int ks) {
    float aU0[4], aU1[4], aR0[4], aR1[4];
#pragma unroll
    for (int r = 0; r < 4; ++r) { aU0[r] = 0.f; aU1[r] = 0.f; aR0[r] = 0.f; aR1[r] = 0.f; }
    const float2* pu = (const float2*)(g_w1t[0] + (size_t)ks * KH * GU) + p;
    const float2* pr = (const float2*)(g_w1t[1] + (size_t)ks * KH * GU) + p;
    const float* yc = ycT + ks * KH * 4;
    float2 uA[6], rA[6], uB[6], rB[6];
#pragma unroll
    for (int kk = 0; kk < 6; ++kk) { uA[kk] = pu[kk * 100]; rA[kk] = pr[kk * 100]; }
#pragma unroll 1
    for (int i = 0; i < 7; ++i) {
        int tB = 2 * i + 1;
#pragma unroll
        for (int kk = 0; kk < 6; ++kk) {
            uB[kk] = pu[(tB * 6 + kk) * 100];
            rB[kk] = pr[(tB * 6 + kk) * 100];
        }
#pragma unroll
        for (int kk = 0; kk < 6; ++kk) {
            int k = 2 * i * 6 + kk;
            float4 yv = *(const float4*)(yc + k * 4);
            float2 wu = uA[kk], wr = rA[kk];
            aU0[0] += yv.x * wu.x; aU0[1] += yv.y * wu.x; aU0[2] += yv.z * wu.x; aU0[3] += yv.w * wu.x;
            aU1[0] += yv.x * wu.y; aU1[1] += yv.y * wu.y; aU1[2] += yv.z * wu.y; aU1[3] += yv.w * wu.y;
            aR0[0] += yv.x * wr.x; aR0[1] += yv.y * wr.x; aR0[2] += yv.z * wr.x; aR0[3] += yv.w * wr.x;
            aR1[0] += yv.x * wr.y; aR1[1] += yv.y * wr.y; aR1[2] += yv.z * wr.y; aR1[3] += yv.w * wr.y;
        }
        if (i < 6) {
            int tA = 2 * i + 2;
#pragma unroll
            for (int kk = 0; kk < 6; ++kk) {
                uA[kk] = pu[(tA * 6 + kk) * 100];
                rA[kk] = pr[(tA * 6 + kk) * 100];
            }
        }
#pragma unroll
        for (int kk = 0; kk < 6; ++kk) {
            int k = tB * 6 + kk;
            float4 yv = *(const float4*)(yc + k * 4);
            float2 wu = uB[kk], wr = rB[kk];
            aU0[0] += yv.x * wu.x; aU0[1] += yv.y * wu.x; aU0[2] += yv.z * wu.x; aU0[3] += yv.w * wu.x;
            aU1[0] += yv.x * wu.y; aU1[1] += yv.y * wu.y; aU1[2] += yv.z * wu.y; aU1[3] += yv.w * wu.y;
            aR0[0] += yv.x * wr.x; aR0[1] += yv.y * wr.x; aR0[2] += yv.z * wr.x; aR0[3] += yv.w * wr.x;
            aR1[0] += yv.x * wr.y; aR1[1] += yv.y * wr.y; aR1[2] += yv.z * wr.y; aR1[3] += yv.w * wr.y;
        }
    }
    // pL1 layout [g][ks][j][4]
    *(float4*)(pL1 + ks * 800 + p * 4)                = make_float4(aU0[0], aU0[1], aU0[2], aU0[3]);
    *(float4*)(pL1 + ks * 800 + (p + 100) * 4)        = make_float4(aU1[0], aU1[1], aU1[2], aU1[3]);
    *(float4*)(pL1 + 1600 + ks * 800 + p * 4)         = make_float4(aR0[0], aR0[1], aR0[2], aR0[3]);
    *(float4*)(pL1 + 1600 + ks * 800 + (p + 100) * 4) = make_float4(aR1[0], aR1[1], aR1[2], aR1[3]);
}

// ---- GRU n l1: j-paired, K-split 2, ping-pong prefetch ----
__device__ __forceinline__ void gru_l1_single_ks(const float* __restrict__ ycT,
                                                 float* __restrict__ pN,
                                                 int p, int ks) {
    float a0[4], a1[4];
#pragma unroll
    for (int r = 0; r < 4; ++r) { a0[r] = 0.f; a1[r] = 0.f; }
    const float2* pn_ = (const float2*)(g_w1t[2] + (size_t)ks * KH * GU) + p;
    const float* yc = ycT + ks * KH * 4;
    float2 nA[6], nB[6];
#pragma unroll
    for (int kk = 0; kk < 6; ++kk) nA[kk] = pn_[kk * 100];
#pragma unroll 1
    for (int i = 0; i < 7; ++i) {
        int tB = 2 * i + 1;
#pragma unroll
        for (int kk = 0; kk < 6; ++kk) nB[kk] = pn_[(tB * 6 + kk) * 100];
#pragma unroll
        for (int kk = 0; kk < 6; ++kk) {
            int k = 2 * i * 6 + kk;
            float4 yv = *(const float4*)(yc + k * 4);
            float2 w = nA[kk];
            a0[0] += yv.x * w.x; a0[1] += yv.y * w.x; a0[2] += yv.z * w.x; a0[3] += yv.w * w.x;
            a1[0] += yv.x * w.y; a1[1] += yv.y * w.y; a1[2] += yv.z * w.y; a1[3] += yv.w * w.y;
        }
        if (i < 6) {
            int tA = 2 * i + 2;
#pragma unroll
            for (int kk = 0; kk < 6; ++kk) nA[kk] = pn_[(tA * 6 + kk) * 100];
        }
#pragma unroll
        for (int kk = 0; kk < 6; ++kk) {
            int k = tB * 6 + kk;
            float4 yv = *(const float4*)(yc + k * 4);
            float2 w = nB[kk];
            a0[0] += yv.x * w.x; a0[1] += yv.y * w.x; a0[2] += yv.z * w.x; a0[3] += yv.w * w.x;
            a1[0] += yv.x * w.y; a1[1] += yv.y * w.y; a1[2] += yv.z * w.y; a1[3] += yv.w * w.y;
        }
    }
    *(float4*)(pN + ks * 800 + p * 4)         = make_float4(a0[0], a0[1], a0[2], a0[3]);
    *(float4*)(pN + ks * 800 + (p + 100) * 4) = make_float4(a1[0], a1[1], a1[2], a1[3]);
}

// encoder MLP: l1 direct (200 thr, 2 rows each), l2 partials (200 thr, 4-row)
__device__ __forceinline__ void enc_eval(const float* __restrict__ ew1,
                                         const float* __restrict__ eb1,
                                         const float* __restrict__ ew2,
                                         const float* __restrict__ ytmpT,
                                         float* __restrict__ hencT,
                                         float* __restrict__ pe, int tid) {
    if (tid < 200) {
        int j = tid % UNI, rq = tid / UNI;   // rows 2rq, 2rq+1
        float a0 = eb1[j], a1 = a0;
#pragma unroll
        for (int k = 0; k < LL; ++k) {
            float w = ew1[k * UNI + j];
            float2 yv = *(const float2*)(ytmpT + k * 4 + 2 * rq);
            a0 += yv.x * w; a1 += yv.y * w;
        }
        *(float2*)(hencT + j * 4 + 2 * rq) = make_float2(fast_tanh(a0), fast_tanh(a1));
    }
    __syncthreads();
    if (tid < 200) {
        int jj = tid % LL, ks = tid / LL;   // ks 0..9, K=10
        float a[4];
#pragma unroll
        for (int r = 0; r < 4; ++r) a[r] = 0.f;
#pragma unroll
        for (int k = ks * 10; k < ks * 10 + 10; ++k) {
            float w = ew2[k * LL + jj];
            float4 y0 = *(const float4*)(hencT + k * 4);
            a[0] += y0.x * w; a[1] += y0.y * w; a[2] += y0.z * w; a[3] += y0.w * w;
        }
        *(float4*)(pe + ks * 80 + jj * 4) = make_float4(a[0], a[1], a[2], a[3]);
    }
    __syncthreads();
}

#define ENC_K(tidv) (pe[(tidv)] + pe[80 + (tidv)] + pe[160 + (tidv)] + pe[240 + (tidv)] + \
                     pe[320 + (tidv)] + pe[400 + (tidv)] + pe[480 + (tidv)] + pe[560 + (tidv)] + \
                     pe[640 + (tidv)] + pe[720 + (tidv)] + eb2[(tidv) >> 2])

// decoder MLP: l1 direct; l2/l3 j-paired from transposed smem weights
__device__ __forceinline__ void dec_eval(const float* __restrict__ dw1,
                                         const float* __restrict__ db1,
                                         const float* __restrict__ dw2t,
                                         const float* __restrict__ db2,
                                         const float* __restrict__ dw3t,
                                         const float* __restrict__ zin,
                                         float* __restrict__ h1T,
                                         float* __restrict__ h2T,
                                         float* __restrict__ pd2,
                                         float* __restrict__ pd3, int tid) {
    if (tid < 200) {
        int j = tid % UNI, rq = tid / UNI;
        float a0 = db1[j], a1 = a0;
#pragma unroll 8
        for (int k = 0; k < LATD; ++k) {
            float w = dw1[k * UNI + j];
            float2 zv = *(const float2*)(zin + k * 4 + 2 * rq);
            a0 += zv.x * w; a1 += zv.y * w;
        }
        *(float2*)(h1T + j * 4 + 2 * rq) = make_float2(fast_tanh(a0), fast_tanh(a1));
    }
    __syncthreads();
    // l2: pairs (j, j+50), ks4, K=25
    if (tid < 200) {
        int pr = tid % 50, ks = tid / 50;
        const float2* wp = (const float2*)dw2t + pr;
        float a0[4], a1[4];
#pragma unroll
        for (int r = 0; r < 4; ++r) { a0[r] = 0.f; a1[r] = 0.f; }
#pragma unroll 5
        for (int k = ks * 25; k < ks * 25 + 25; ++k) {
            float2 w = wp[k * 50];
            float4 z0 = *(const float4*)(h1T + k * 4);
            a0[0] += z0.x * w.x; a0[1] += z0.y * w.x; a0[2] += z0.z * w.x; a0[3] += z0.w * w.x;
            a1[0] += z0.x * w.y; a1[1] += z0.y * w.y; a1[2] += z0.z * w.y; a1[3] += z0.w * w.y;
        }
        *(float4*)(pd2 + ks * 400 + pr * 4)        = make_float4(a0[0], a0[1], a0[2], a0[3]);
        *(float4*)(pd2 + ks * 400 + (pr + 50) * 4) = make_float4(a1[0], a1[1], a1[2], a1[3]);
    }
    __syncthreads();
    for (int i = tid; i < 400; i += NTHR)
        h2T[i] = fast_tanh(pd2[i] + pd2[400 + i] + pd2[800 + i] + pd2[1200 + i] + db2[i >> 2]);
    __syncthreads();
    // l3: pairs (jj, jj+16), ks10, K=10
    if (tid < 160) {
        int pr = tid % 16, ks = tid / 16;
        const float2* wp = (const float2*)dw3t + pr;
        float a0[4], a1[4];
#pragma unroll
        for (int r = 0; r < 4; ++r) { a0[r] = 0.f; a1[r] = 0.f; }
#pragma unroll
        for (int k = ks * 10; k < ks * 10 + 10; ++k) {
            float2 w = wp[k * 16];
            float4 z0 = *(const float4*)(h2T + k * 4);
            a0[0] += z0.x * w.x; a0[1] += z0.y * w.x; a0[2] += z0.z * w.x; a0[3] += z0.w * w.x;
            a1[0] += z0.x * w.y; a1[1] += z0.y * w.y; a1[2] += z0.z * w.y; a1[3] += z0.w * w.y;
        }
        *(float4*)(pd3 + ks * 128 + pr * 4)        = make_float4(a0[0], a0[1], a0[2], a0[3]);
        *(float4*)(pd3 + ks * 128 + (pr + 16) * 4) = make_float4(a1[0], a1[1], a1[2], a1[3]);
    }
    __syncthreads();
}

#define DEC_K(tidv) (pd3[(tidv)] + pd3[128 + (tidv)] + pd3[256 + (tidv)] + pd3[384 + (tidv)] + \
                     pd3[512 + (tidv)] + pd3[640 + (tidv)] + pd3[768 + (tidv)] + pd3[896 + (tidv)] + \
                     pd3[1024 + (tidv)] + pd3[1152 + (tidv)] + db3[(tidv) >> 2])

extern "C" __global__ void __launch_bounds__(NTHR, 2)
latent_ode_main(const float* __restrict__ truth, const float* __restrict__ tarr,
                const int* __restrict__ obs_idx, const float* __restrict__ eps,
                const float* __restrict__ ew1g, const float* __restrict__ eb1g,
                const float* __restrict__ ew2g, const float* __restrict__ eb2g,
                const float* __restrict__ uw1, const float* __restrict__ ub1g,
                const float* __restrict__ uw2g, const float* __restrict__ ub2g,
                const float* __restrict__ rw1, const float* __restrict__ rb1g,
                const float* __restrict__ rw2g, const float* __restrict__ rb2g,
                const float* __restrict__ nw1, const float* __restrict__ nb1g,
                const float* __restrict__ nw2g, const float* __restrict__ nb2g,
                const float* __restrict__ z0w1, const float* __restrict__ z0b1,
                const float* __restrict__ z0w2, const float* __restrict__ z0b2,
                const float* __restrict__ dw1g, const float* __restrict__ db1g,
                const float* __restrict__ dw2g, const float* __restrict__ db2g,
                const float* __restrict__ dw3g, const float* __restrict__ db3g,
                const float* __restrict__ owg, const float* __restrict__ obg,
                float* __restrict__ out) {
    extern __shared__ float s[];
    const int tid = threadIdx.x;
    const int b0 = blockIdx.x * ROWS;

    float* zT = s;           // [32][4] k-major, persistent
    float* P  = s + 256;

    // ---------------- encoder smem layout ----------------
    float* ew1   = P;            // 2000
    float* ew2   = P + 2000;     // 2000
    float* eb1   = P + 4000;     // 100
    float* eb2   = P + 4100;     // 20 (pad to 4128)
    float* nw2t  = P + 4128;     // 8000 (pair-interleaved)
    float* ub1   = P + 12128;    // 200
    float* rb1   = P + 12328;    // 200
    float* nb1   = P + 12528;    // 200
    float* ub2   = P + 12728;    // 40
    float* rb2   = P + 12768;    // 40
    float* nb2   = P + 12808;    // 40
    float* csu   = P + 12848;    // 200
    float* csr   = P + 13048;    // 200
    float* csn   = P + 13248;    // 200
    float* y     = P + 13448;    // 160  [4][40]
    float* ycT   = P + 13608;    // 672  [168][4]
    float* ytmpT = P + 14280;    // 80
    float* accT  = P + 14360;    // 80
    float* hencT = P + 14440;    // 400
    float* pe    = P + 14840;    // 800  [10][20][4]
    float* hTa   = P + 15640;    // 800  [200][4]
    float* hTb   = P + 16440;    // 800
    float* pL1   = P + 17240;    // 3200 [2g][2ks][200][4]
    float* p2    = P + 20440;    // 2560 [2g][8ks][40][4]
    float* pn    = P + 23000;    // 1280 [8ks][40][4]
    float* u_    = P + 24280;    // 160  [4][40]
    // shared tail (beyond both alias regions):
    float* dts   = P + 25824;    // 140
    float* iob   = P + 25964;    // 140
    float* ddt   = P + 26104;    // 200 (end 26304)

    for (int i = tid; i < 2000; i += NTHR) { ew1[i] = ew1g[i]; ew2[i] = ew2g[i]; }
    for (int i = tid; i < 100;  i += NTHR) eb1[i] = eb1g[i];
    for (int i = tid; i < 20;   i += NTHR) eb2[i] = eb2g[i];
    for (int i = tid; i < 8000; i += NTHR) {
        int k = i / 40, j = i % 40;
        nw2t[k * 40 + 2 * (j % 20) + (j / 20)] = nw2g[i];
    }
    for (int i = tid; i < 200;  i += NTHR) {
        ub1[i] = ub1g[i]; rb1[i] = rb1g[i]; nb1[i] = nb1g[i];
        csu[i] = g_colsum[i]; csr[i] = g_colsum[200 + i]; csn[i] = g_colsum[400 + i];
    }
    for (int i = tid; i < 40; i += NTHR) { ub2[i] = ub2g[i]; rb2[i] = rb2g[i]; nb2[i] = nb2g[i]; }
    for (int i = tid; i < ROWS * 40; i += NTHR) y[i] = 0.f;
    for (int i = tid; i < TOBS; i += NTHR) {
        int io = obs_idx[TOBS - 1 - i];
        iob[i] = __int_as_float(io);
        dts[i] = (i > 0) ? (tarr[io] - tarr[obs_idx[TOBS - i]]) : 0.f;
    }
    for (int i = tid; i < TT - 1; i += NTHR) ddt[i] = tarr[i + 1] - tarr[i];
    __syncthreads();

    // ================= encoder scan =================
    for (int st = 0; st < TOBS; ++st) {
        int io = __float_as_int(iob[st]);
        float dt = dts[st];

        // ---- RK4 on ym ----
        if (tid < 80) { int j = tid >> 2, r = tid & 3; ytmpT[tid] = y[r * 40 + j]; }
        __syncthreads();
        enc_eval(ew1, eb1, ew2, ytmpT, hencT, pe, tid);
        if (tid < 80) {
            int j = tid >> 2, r = tid & 3;
            float kv = ENC_K(tid);
            accT[tid] = kv;
            ytmpT[tid] = y[r * 40 + j] + 0.5f * dt * kv;
        }
        __syncthreads();
        enc_eval(ew1, eb1, ew2, ytmpT, hencT, pe, tid);
        if (tid < 80) {
            int j = tid >> 2, r = tid & 3;
            float kv = ENC_K(tid);
            accT[tid] += 2.f * kv;
            ytmpT[tid] = y[r * 40 + j] + 0.5f * dt * kv;
        }
        __syncthreads();
        enc_eval(ew1, eb1, ew2, ytmpT, hencT, pe, tid);
        if (tid < 80) {
            int j = tid >> 2, r = tid & 3;
            float kv = ENC_K(tid);
            accT[tid] += 2.f * kv;
            ytmpT[tid] = y[r * 40 + j] + dt * kv;
        }
        __syncthreads();
        enc_eval(ew1, eb1, ew2, ytmpT, hencT, pe, tid);
        if (tid < 80) {
            int j = tid >> 2, r = tid & 3;
            float kv = ENC_K(tid);
            y[r * 40 + j] += dt * (1.f / 6.f) * (accT[tid] + kv);
        }
        __syncthreads();

        // ---- build ycT ----
        for (int i = tid; i < GIN * ROWS; i += NTHR) {
            int k = i >> 2, r = i & 3;
            ycT[i] = (k < 40) ? y[r * 40 + k]
                              : truth[(size_t)io * (BB * DD) + (size_t)(b0 + r) * DD + (k - 40)];
        }
        __syncthreads();

        // ---- u,r layer1 (j-paired, K-split 2, 200 thr) ----
        if (tid < 200)
            gru_l1_dual_ks(ycT, pL1, tid % 100, tid / 100);
        __syncthreads();
        // reduce + bias + tanh (1600 items)
        for (int i = tid; i < 1600; i += NTHR) {
            int g = i / 800, rem = i % 800, j = rem >> 2;
            float base = g ? (csr[j] + rb1[j]) : (csu[j] + ub1[j]);
            float v = pL1[g * 1600 + rem] + pL1[g * 1600 + 800 + rem] + base;
            (g ? hTb : hTa)[rem] = fast_tanh(v);
        }
        __syncthreads();

        // ---- u,r layer2 (j-paired, ks8 K=25, 320 thr; weights streamed from g_w2t) ----
        if (tid < 320) {
            int g = tid / 160, q = tid % 160, pr = q % 20, ks = q / 20;
            const float* hT = g ? hTb : hTa;
            const float2* wp = (const float2*)g_w2t[g] + pr;
            float a0[4], a1[4];
#pragma unroll
            for (int r = 0; r < 4; ++r) { a0[r] = 0.f; a1[r] = 0.f; }
            int kbase = ks * 25;
            float2 wbuf[5];
#pragma unroll
            for (int kk = 0; kk < 5; ++kk) wbuf[kk] = wp[(kbase + kk) * 20];
#pragma unroll 1
            for (int t = 0; t < 5; ++t) {
                float2 nb[5];
                if (t + 1 < 5) {
#pragma unroll
                    for (int kk = 0; kk < 5; ++kk) nb[kk] = wp[(kbase + (t + 1) * 5 + kk) * 20];
                }
#pragma unroll
                for (int kk = 0; kk < 5; ++kk) {
                    int k = kbase + t * 5 + kk;
                    float4 h0 = *(const float4*)(hT + k * 4);
                    float2 w = wbuf[kk];
                    a0[0] += h0.x * w.x; a0[1] += h0.y * w.x; a0[2] += h0.z * w.x; a0[3] += h0.w * w.x;
                    a1[0] += h0.x * w.y; a1[1] += h0.y * w.y; a1[2] += h0.z * w.y; a1[3] += h0.w * w.y;
                }
                if (t + 1 < 5) {
#pragma unroll
                    for (int kk = 0; kk < 5; ++kk) wbuf[kk] = nb[kk];
                }
            }
            float* pb = p2 + g * 1280 + ks * 160;
            *(float4*)(pb + pr * 4)        = make_float4(a0[0], a0[1], a0[2], a0[3]);
            *(float4*)(pb + (pr + 20) * 4) = make_float4(a1[0], a1[1], a1[2], a1[3]);
        }
        __syncthreads();
        // reduce + sigmoid; g==1 (r gate) scales ycT in place, g==0 stores u_
        if (tid < 320) {
            int g = tid / 160, rem = tid % 160, jj = rem >> 2, r = rem & 3;
            const float* p = p2 + g * 1280;
            float a = p[rem] + p[160 + rem] + p[320 + rem] + p[480 + rem]
                    + p[640 + rem] + p[800 + rem] + p[960 + rem] + p[1120 + rem]
                    + (g ? rb2 : ub2)[jj];
            float sg = fast_sigmoid(a);
            if (g) ycT[rem] *= sg;   // rem == jj*4+r, jj<40: y-part of ycT
            else   u_[r * 40 + jj] = sg;
        }
        __syncthreads();

        // ---- n layer1 (j-paired, K-split 2, 200 thr; ycT already r-scaled) ----
        if (tid < 200)
            gru_l1_single_ks(ycT, pL1, tid % 100, tid / 100);
        __syncthreads();
        for (int i = tid; i < 800; i += NTHR) {
            int j = i >> 2;
            hTa[i] = fast_tanh(pL1[i] + pL1[800 + i] + csn[j] + nb1[j]);
        }
        __syncthreads();

        // ---- n layer2 (j-paired, ks8 K=25, 160 thr; nw2t in smem) ----
        if (tid < 160) {
            int pr = tid % 20, ks = tid / 20;
            const float2* wp = (const float2*)nw2t + pr;
            float a0[4], a1[4];
#pragma unroll
            for (int r = 0; r < 4; ++r) { a0[r] = 0.f; a1[r] = 0.f; }
#pragma unroll 5
            for (int k = ks * 25; k < ks * 25 + 25; ++k) {
                float2 w = wp[k * 20];
                float4 h0 = *(const float4*)(hTa + k * 4);
                a0[0] += h0.x * w.x; a0[1] += h0.y * w.x; a0[2] += h0.z * w.x; a0[3] += h0.w * w.x;
                a1[0] += h0.x * w.y; a1[1] += h0.y * w.y; a1[2] += h0.z * w.y; a1[3] += h0.w * w.y;
            }
            *(float4*)(pn + ks * 160 + pr * 4)        = make_float4(a0[0], a0[1], a0[2], a0[3]);
            *(float4*)(pn + ks * 160 + (pr + 20) * 4) = make_float4(a1[0], a1[1], a1[2], a1[3]);
        }
        __syncthreads();
        // reduce + state update
        if (tid < 160) {
            int jj = tid >> 2, r = tid & 3;
            float a = pn[tid] + pn[160 + tid] + pn[320 + tid] + pn[480 + tid]
                    + pn[640 + tid] + pn[800 + tid] + pn[960 + tid] + pn[1120 + tid] + nb2[jj];
            float val = (jj < LL) ? a : fabsf(a);
            float uu = u_[r * 40 + jj];
            y[r * 40 + jj] = (1.f - uu) * val + uu * y[r * 40 + jj];
        }
        __syncthreads();
    }

    // ================= z0 head (once) =================
    for (int i = tid; i < ROWS * UNI; i += NTHR) {
        int r = i / UNI, j = i % UNI;
        float a = z0b1[j];
#pragma unroll 4
        for (int k = 0; k < 40; ++k) a += y[r * 40 + k] * z0w1[k * UNI + j];
        hencT[i] = fast_tanh(a);
    }
    __syncthreads();
    if (tid < 256) {
        int r = tid / 64, j = tid % 64;
        float a = z0b2[j];
#pragma unroll 4
        for (int k = 0; k < UNI; ++k) a += hencT[r * UNI + k] * z0w2[k * 64 + j];
        hTa[r * 64 + j] = a;
    }
    __syncthreads();
    if (tid < 128) {
        int r = tid >> 5, j = tid & 31;
        float m = hTa[r * 64 + j];
        float sd = fabsf(hTa[r * 64 + 32 + j]);
        zT[j * 4 + r] = m + eps[(size_t)(b0 + r) * LATD + j] * sd;
    }
    __syncthreads();

    // ---------------- decoder smem layout (aliases P; tail beyond) ----------------
    float* dw1   = P;             // 3200
    float* dw2t  = P + 3200;      // 10000 (pair-interleaved)
    float* dw3t  = P + 13200;     // 3200 (pair-interleaved)
    float* db1   = P + 16400;     // 100
    float* db2   = P + 16500;     // 100
    float* db3   = P + 16600;     // 32
    float* owt   = P + 16632;     // 4096 (pair-interleaved)
    float* ob    = P + 20728;     // 128
    float* h1T   = P + 20856;     // 400
    float* h2T   = P + 21256;     // 400
    float* ztmpT = P + 21656;     // 128
    float* zacc  = P + 21784;     // 128
    float* pd2   = P + 21912;     // 1600 [4][100][4]
    float* pd3   = P + 23512;     // 1280 [10][32][4]
    float* pp    = P + 24792;     // 1024 [2][128][4]  (end 25816)

    for (int i = tid; i < 3200;  i += NTHR) dw1[i] = dw1g[i];
    for (int i = tid; i < 10000; i += NTHR) {
        int k = i / 100, j = i % 100;
        dw2t[k * 100 + 2 * (j % 50) + (j / 50)] = dw2g[i];
    }
    for (int i = tid; i < 3200; i += NTHR) {
        int k = i / 32, j = i % 32;
        dw3t[k * 32 + 2 * (j % 16) + (j / 16)] = dw3g[i];
    }
    for (int i = tid; i < 4096; i += NTHR) {
        int k = i / 128, d = i % 128;
        owt[k * 128 + 2 * (d % 64) + (d / 64)] = owg[i];
    }
    for (int i = tid; i < 100;   i += NTHR) { db1[i] = db1g[i]; db2[i] = db2g[i]; }
    for (int i = tid; i < 32;    i += NTHR) db3[i] = db3g[i];
    for (int i = tid; i < 128;   i += NTHR) ob[i] = obg[i];
    __syncthreads();

    // ================= decoder scan + projection =================
    for (int ti = 0; ti < TT; ++ti) {
        if (ti > 0) {
            float dt = ddt[ti - 1];
            if (tid < 128) ztmpT[tid] = zT[tid];
            __syncthreads();
            dec_eval(dw1, db1, dw2t, db2, dw3t, ztmpT, h1T, h2T, pd2, pd3, tid);
            if (tid < 128) {
                float kv = DEC_K(tid);
                zacc[tid] = kv;
                ztmpT[tid] = zT[tid] + 0.5f * dt * kv;
            }
            __syncthreads();
            dec_eval(dw1, db1, dw2t, db2, dw3t, ztmpT, h1T, h2T, pd2, pd3, tid);
            if (tid < 128) {
                float kv = DEC_K(tid);
                zacc[tid] += 2.f * kv;
                ztmpT[tid] = zT[tid] + 0.5f * dt * kv;
            }
            __syncthreads();
            dec_eval(dw1, db1, dw2t, db2, dw3t, ztmpT, h1T, h2T, pd2, pd3, tid);
            if (tid < 128) {
                float kv = DEC_K(tid);
                zacc[tid] += 2.f * kv;
                ztmpT[tid] = zT[tid] + dt * kv;
            }
            __syncthreads();
            dec_eval(dw1, db1, dw2t, db2, dw3t, ztmpT, h1T, h2T, pd2, pd3, tid);
            if (tid < 128) {
                float kv = DEC_K(tid);
                zT[tid] += dt * (1.f / 6.f) * (zacc[tid] + kv);
            }
            __syncthreads();
        }

        // output projection (d-paired, ks2 K=16, 128 thr)
        if (tid < 128) {
            int pr = tid % 64, h = tid / 64;
            const float2* wp = (const float2*)owt + pr;
            float a0[4], a1[4];
#pragma unroll
            for (int r = 0; r < 4; ++r) { a0[r] = 0.f; a1[r] = 0.f; }
#pragma unroll
            for (int k = h * 16; k < h * 16 + 16; ++k) {
                float2 w = wp[k * 64];
                float4 z0 = *(const float4*)(zT + k * 4);
                a0[0] += z0.x * w.x; a0[1] += z0.y * w.x; a0[2] += z0.z * w.x; a0[3] += z0.w * w.x;
                a1[0] += z0.x * w.y; a1[1] += z0.y * w.y; a1[2] += z0.z * w.y; a1[3] += z0.w * w.y;
            }
            *(float4*)(pp + h * 512 + pr * 4)        = make_float4(a0[0], a0[1], a0[2], a0[3]);
            *(float4*)(pp + h * 512 + (pr + 64) * 4) = make_float4(a1[0], a1[1], a1[2], a1[3]);
        }
        __syncthreads();
        if (tid < DD) {
            int d = tid;
#pragma unroll
            for (int r = 0; r < 4; ++r)
                out[(size_t)(b0 + r) * (TT * DD) + (size_t)ti * DD + d] =
                    pp[d * 4 + r] + pp[512 + d * 4 + r] + ob[d];
        }
        __syncthreads();
    }
}

extern "C" void kernel_launch(void* const* d_in, const int* in_sizes, int n_in,
                              void* d_out, int out_size) {
    (void)in_sizes; (void)n_in; (void)out_size;
    size_t smem = (size_t)SM_FLOATS * sizeof(float);
    cudaFuncSetAttribute(latent_ode_main, cudaFuncAttributeMaxDynamicSharedMemorySize, (int)smem);

    prep_kernel<<<3, 256>>>((const float*)d_in[8], (const float*)d_in[12], (const float*)d_in[16],
                            (const float*)d_in[10], (const float*)d_in[14]);

    latent_ode_main<<<NBLK, NTHR, smem>>>(
        (const float*)d_in[0], (const float*)d_in[1], (const int*)d_in[2], (const float*)d_in[3],
        (const float*)d_in[4],  (const float*)d_in[5],  (const float*)d_in[6],  (const float*)d_in[7],
        (const float*)d_in[8],  (const float*)d_in[9],  (const float*)d_in[10], (const float*)d_in[11],
        (const float*)d_in[12], (const float*)d_in[13], (const float*)d_in[14], (const float*)d_in[15],
        (const float*)d_in[16], (const float*)d_in[17], (const float*)d_in[18], (const float*)d_in[19],
        (const float*)d_in[20], (const float*)d_in[21], (const float*)d_in[22], (const float*)d_in[23],
        (const float*)d_in[24], (const float*)d_in[25], (const float*)d_in[26], (const float*)d_in[27],
        (const float*)d_in[28], (const float*)d_in[29], (const float*)d_in[30], (const float*)d_in[31],
        (float*)d_out);
}